// round 9
// baseline (speedup 1.0000x reference)
#include <cuda_runtime.h>

// ---------------------------------------------------------------------------
// SSIM (5x5 Gaussian, sigma=1.5, SAME zero padding), fused single kernel.
// R9: 2 px/thread with even/odd-split block-wide smem row buffer.
//     - float2 LDG/STG (aligned), 6 unit-stride conflict-free LDS.64 per
//       channel cover BOTH columns' 5-tap windows -> ~2x fewer L1 wavefronts
//       (R8 showed L1=78% saturated).
//     - block-wide buffer: inter-warp halos come from neighbors' entries;
//       only 2 edge float2 per img per channel, loaded by threads 0..5.
//     - keeps (s,d)=(a+b,a-b) transform and 1-row software prefetch.
// ---------------------------------------------------------------------------

constexpr int W     = 512;
constexpr int H     = 512;
constexpr int C     = 3;
constexpr int NB    = 16;
constexpr int BX    = 256;          // output cols per block (128 thr x 2)
constexpr int ROWS  = 16;           // output rows per block
constexpr int STEPS = ROWS + 4;     // 20 input rows (divisible by 5)

typedef unsigned long long u64;

__device__ __forceinline__ u64 pk2(float lo, float hi) {
    u64 r;
    asm("mov.b64 %0, {%1, %2};" : "=l"(r) : "f"(lo), "f"(hi));
    return r;
}
__device__ __forceinline__ void up2(u64 v, float& lo, float& hi) {
    asm("mov.b64 {%0, %1}, %2;" : "=f"(lo), "=f"(hi) : "l"(v));
}
__device__ __forceinline__ u64 fma2_(u64 a, u64 b, u64 c) {
    u64 d;
    asm("fma.rn.f32x2 %0, %1, %2, %3;" : "=l"(d) : "l"(a), "l"(b), "l"(c));
    return d;
}
__device__ __forceinline__ u64 mul2_(u64 a, u64 b) {
    u64 d;
    asm("mul.rn.f32x2 %0, %1, %2;" : "=l"(d) : "l"(a), "l"(b));
    return d;
}

__global__ __launch_bounds__(128, 3)
void ssim_kernel(const float* __restrict__ img1,
                 const float* __restrict__ img2,
                 const float* __restrict__ win,
                 float* __restrict__ out)
{
    // Block-wide row buffers: entry 1+i = col x0b+2i (even) / x0b+2i+1 (odd),
    // entry 0 = left halo cols (x0b-2, x0b-1), entry 129 = right halo
    // (x0b+256, x0b+257). (s,d) pairs.
    __shared__ float2 sE[C][130];
    __shared__ float2 sO[C][130];

    const int t   = threadIdx.x;           // 0..127
    const int b   = blockIdx.z;
    const int y0  = blockIdx.y * ROWS;
    const int x0b = blockIdx.x * BX;
    const int xo  = x0b + 2 * t;           // this thread's even output col

    // Recover separable 1D Gaussian: g[j] = w2d[2][j] / sqrt(w2d[2][2])
    const float gc = sqrtf(win[12]);
    u64 wg[5];
#pragma unroll
    for (int j = 0; j < 5; ++j) {
        const float gj = __fdividef(win[10 + j], gc);
        wg[j] = pk2(gj, gj);
    }

    int cbase[C];
#pragma unroll
    for (int c = 0; c < C; ++c) cbase[c] = ((b * C + c) * H) * W;

    // Halo duty: threads 0..5 each own one (side, channel) edge float2.
    const int  hside = t & 1;              // 0 = left, 1 = right
    const int  hc    = t >> 1;             // channel 0..2
    const bool hduty = (t < 6);
    const int  hx    = hside ? (x0b + BX) : (x0b - 2);
    const bool hxok  = hduty && (hside ? (x0b + BX < W) : (x0b >= 2));

    // Rolling horizontal-filtered state: 5 row slots, per channel, per parity.
    u64 heSD[C][5], heSQ[C][5], hoSD[C][5], hoSQ[C][5];

    // Prefetch registers (one row ahead).
    float2 p1[C], p2[C];
    float2 hh1, hh2;                       // halo (threads 0..5 only)

    auto loadrow = [&](int r) {
        const bool rok = (r >= 0) && (r < H);
        const int rr = (rok ? r : 0) * W;
        float2 t1[C], t2[C];
#pragma unroll
        for (int c = 0; c < C; ++c) {
            const int off = cbase[c] + rr;
            t1[c] = *reinterpret_cast<const float2*>(img1 + off + xo);
            t2[c] = *reinterpret_cast<const float2*>(img2 + off + xo);
        }
        float2 u1 = make_float2(0.f, 0.f), u2 = make_float2(0.f, 0.f);
        if (hxok && rok) {
            const int hoff = cbase[hc] + rr + hx;
            u1 = *reinterpret_cast<const float2*>(img1 + hoff);
            u2 = *reinterpret_cast<const float2*>(img2 + hoff);
        }
#pragma unroll
        for (int c = 0; c < C; ++c) {
            p1[c] = rok ? t1[c] : make_float2(0.f, 0.f);
            p2[c] = rok ? t2[c] : make_float2(0.f, 0.f);
        }
        hh1 = u1; hh2 = u2;
    };

    loadrow(y0 - 2);

    const float C1 = 0.0001f;  // (0.01)^2
    const float C2 = 0.0009f;  // (0.03)^2

    for (int base = 0; base < STEPS; base += 5) {
#pragma unroll
        for (int k = 0; k < 5; ++k) {
            const int s = base + k;

            // ---- store prefetched row as (s,d), even/odd split ----
            __syncthreads();
#pragma unroll
            for (int c = 0; c < C; ++c) {
                sE[c][1 + t] = make_float2(p1[c].x + p2[c].x, p1[c].x - p2[c].x);
                sO[c][1 + t] = make_float2(p1[c].y + p2[c].y, p1[c].y - p2[c].y);
            }
            if (hduty) {
                const int idx = hside ? 129 : 0;
                sE[hc][idx] = make_float2(hh1.x + hh2.x, hh1.x - hh2.x);
                sO[hc][idx] = make_float2(hh1.y + hh2.y, hh1.y - hh2.y);
            }
            __syncthreads();

            // ---- prefetch next row (hidden behind compute below) ----
            loadrow(y0 - 1 + s);

            // ---- horizontal pass: 6 unit-stride LDS.64 per channel feed
            //      both columns' 5-tap windows ----
#pragma unroll
            for (int c = 0; c < C; ++c) {
                const u64* pE = (const u64*)&sE[c][0];
                const u64* pO = (const u64*)&sO[c][0];
                const u64 e0 = pE[t], e1 = pE[t + 1], e2 = pE[t + 2];
                const u64 o0 = pO[t], o1 = pO[t + 1], o2 = pO[t + 2];
                const u64 qe0 = mul2_(e0, e0), qe1 = mul2_(e1, e1), qe2 = mul2_(e2, e2);
                const u64 qo0 = mul2_(o0, o0), qo1 = mul2_(o1, o1), qo2 = mul2_(o2, o2);
                // even col (taps: e0,o0,e1,o1,e2)
                u64 esd = mul2_(e0, wg[0]);
                esd = fma2_(o0, wg[1], esd); esd = fma2_(e1, wg[2], esd);
                esd = fma2_(o1, wg[3], esd); esd = fma2_(e2, wg[4], esd);
                u64 esq = mul2_(qe0, wg[0]);
                esq = fma2_(qo0, wg[1], esq); esq = fma2_(qe1, wg[2], esq);
                esq = fma2_(qo1, wg[3], esq); esq = fma2_(qe2, wg[4], esq);
                // odd col (taps: o0,e1,o1,e2,o2)
                u64 osd = mul2_(o0, wg[0]);
                osd = fma2_(e1, wg[1], osd); osd = fma2_(o1, wg[2], osd);
                osd = fma2_(e2, wg[3], osd); osd = fma2_(o2, wg[4], osd);
                u64 osq = mul2_(qo0, wg[0]);
                osq = fma2_(qe1, wg[1], osq); osq = fma2_(qo1, wg[2], osq);
                osq = fma2_(qe2, wg[3], osq); osq = fma2_(qo2, wg[4], osq);
                heSD[c][s % 5] = esd; heSQ[c][s % 5] = esq;
                hoSD[c][s % 5] = osd; hoSQ[c][s % 5] = osq;
            }

            // ---- vertical pass + epilogue for output row y0+s-4, 2 cols ----
            if (s >= 4) {
                float numE[C], denE[C], numO[C], denO[C];
#pragma unroll
                for (int c = 0; c < C; ++c) {
                    u64 vsd = 0ull, vsq = 0ull, wsd = 0ull, wsq = 0ull;
#pragma unroll
                    for (int j = 0; j < 5; ++j) {
                        const int slot = (s + 1 + j) % 5;  // row s-4+j
                        vsd = fma2_(heSD[c][slot], wg[j], vsd);
                        vsq = fma2_(heSQ[c][slot], wg[j], vsq);
                        wsd = fma2_(hoSD[c][slot], wg[j], wsd);
                        wsq = fma2_(hoSQ[c][slot], wg[j], wsq);
                    }
                    {   // even column
                        float cs, cd, css, csd;
                        up2(vsd, cs, cd); up2(vsq, css, csd);
                        const float cs2 = cs * cs, cd2 = cd * cd;
                        const float m12 = (cs2 - cd2) * 0.25f;
                        const float msq = (cs2 + cd2) * 0.5f;
                        const float cab = (css - csd) * 0.25f;
                        const float csum = (css + csd) * 0.5f;
                        numE[c] = (2.f * m12 + C1) * (2.f * (cab - m12) + C2);
                        denE[c] = (msq + C1) * ((csum - msq) + C2);
                    }
                    {   // odd column
                        float cs, cd, css, csd;
                        up2(wsd, cs, cd); up2(wsq, css, csd);
                        const float cs2 = cs * cs, cd2 = cd * cd;
                        const float m12 = (cs2 - cd2) * 0.25f;
                        const float msq = (cs2 + cd2) * 0.5f;
                        const float cab = (css - csd) * 0.25f;
                        const float csum = (css + csd) * 0.5f;
                        numO[c] = (2.f * m12 + C1) * (2.f * (cab - m12) + C2);
                        denO[c] = (msq + C1) * ((csum - msq) + C2);
                    }
                }
                // One division per column via 3-ratio combine.
                const float de01 = denE[0] * denE[1];
                const float deD  = de01 * denE[2];
                float deN = numE[2] * de01;
                deN = fmaf(numE[0], denE[1] * denE[2], deN);
                deN = fmaf(numE[1], denE[0] * denE[2], deN);
                const float do01 = denO[0] * denO[1];
                const float doD  = do01 * denO[2];
                float doN = numO[2] * do01;
                doN = fmaf(numO[0], denO[1] * denO[2], doN);
                doN = fmaf(numO[1], denO[0] * denO[2], doN);
                const int y = y0 + s - 4;
                const float2 res = make_float2(__fdividef(deN, deD) * (1.f / 3.f),
                                               __fdividef(doN, doD) * (1.f / 3.f));
                *reinterpret_cast<float2*>(out + (b * H + y) * W + xo) = res;
            }
        }
    }
}

extern "C" void kernel_launch(void* const* d_in, const int* in_sizes, int n_in,
                              void* d_out, int out_size)
{
    const float* img1 = (const float*)d_in[0];
    const float* img2 = (const float*)d_in[1];
    const float* win  = (const float*)d_in[2];
    float* out = (float*)d_out;

    dim3 grid(W / BX, H / ROWS, NB);  // (2, 32, 16) = 1024 blocks
    ssim_kernel<<<grid, 128>>>(img1, img2, win, out);
}